// round 9
// baseline (speedup 1.0000x reference)
#include <cuda_runtime.h>
#include <cstdint>

// Gate pipeline, L2-resident chunking (4 chunks x 16 batches):
//   convsel chunk: conv 4x4/s4 -> gate; last block per batch runs exact
//                  K-th-largest radix select (fused tail, counter protocol)
//   mul chunk:     out = in * (gate >= thr ? gate : 0); the chunk's input
//                  (50MB) is still L2-resident from conv -> reads hit L2.
__device__ float    d_gate[64 * 16384];
__device__ unsigned d_thr[64];
__device__ int      d_count[64];    // zero-init; last block resets (replay-safe)

__device__ __forceinline__ unsigned f2key(float f) {
    unsigned u = __float_as_uint(f);
    return (u & 0x80000000u) ? ~u : (u | 0x80000000u);  // monotone float->uint
}

// ---------------------------------------------------------------------------
// convsel: 32 blocks x 512 thr per batch, 16 batches per launch.
// Each thread computes one gate pixel (12 coalesced float4 loads).
// Last-arriving block of each batch runs the register-key radix select
// (warp-private match_any histograms + single-warp shfl suffix scan).
// ---------------------------------------------------------------------------
__global__ void __launch_bounds__(512) gate_convsel_kernel(
        const float4* __restrict__ in, const float* __restrict__ wk,
        int batch0) {
    __shared__ float4 w[12];
    __shared__ unsigned hist[16][256];
    __shared__ int cnt[256];
    __shared__ unsigned s_prefix;
    __shared__ int s_k;
    __shared__ int s_rank;

    const int t = threadIdx.x;
    if (t < 12) w[t] = reinterpret_cast<const float4*>(wk)[t];
    __syncthreads();

    const int bin_chunk = blockIdx.x >> 5;          // batch within chunk
    const int blk = blockIdx.x & 31;                // block within batch
    const int b = batch0 + bin_chunk;               // global batch
    const int pix = blk * 512 + t;                  // [0,16384) gate pixel
    const int x = pix & 127;
    const int y = pix >> 7;

    // ---- conv ----
    const float4* base = in + (size_t)b * 196608 + x;
    float sum = 0.0f;
#pragma unroll
    for (int c = 0; c < 3; c++) {
#pragma unroll
        for (int i = 0; i < 4; i++) {
            float4 v = base[c * 65536 + (4 * y + i) * 128];
            float4 ww = w[c * 4 + i];
            sum += v.x * ww.x + v.y * ww.y + v.z * ww.z + v.w * ww.w;
        }
    }
    d_gate[b * 16384 + pix] = sum;

    // ---- arrival: last block of this batch runs the select ----
    __threadfence();
    __syncthreads();
    if (t == 0) s_rank = atomicAdd(&d_count[b], 1);
    __syncthreads();
    if (s_rank != 31) return;

    const int warp = t >> 5;
    const int lane = t & 31;

    // one-shot vectorized key load (L2-hot: just written)
    unsigned key[32];
    const float4* g4 = reinterpret_cast<const float4*>(d_gate + b * 16384);
#pragma unroll
    for (int i = 0; i < 8; i++) {
        float4 v = g4[t + i * 512];
        key[4 * i + 0] = f2key(v.x);
        key[4 * i + 1] = f2key(v.y);
        key[4 * i + 2] = f2key(v.z);
        key[4 * i + 3] = f2key(v.w);
    }

    if (t == 0) { s_prefix = 0u; s_k = 4096; }

#pragma unroll
    for (int pass = 0; pass < 4; pass++) {
        const int shift = 24 - 8 * pass;
        for (int i = t; i < 16 * 256; i += 512)
            (&hist[0][0])[i] = 0u;
        __syncthreads();

        const unsigned pmask = pass ? (0xFFFFFFFFu << (32 - 8 * pass)) : 0u;
        const unsigned prefix = s_prefix;
        const int kcur = s_k;

#pragma unroll
        for (int i = 0; i < 32; i++) {
            unsigned u = key[i];
            unsigned bn = ((u & pmask) == prefix) ? ((u >> shift) & 0xFFu)
                                                  : 0xFFFFFFFFu;
            unsigned same = __match_any_sync(0xFFFFFFFFu, bn);
            if (bn != 0xFFFFFFFFu && lane == (__ffs(same) - 1))
                hist[warp][bn] += __popc(same);      // warp-private
        }
        __syncthreads();

        if (t < 256) {
            int c = 0;
#pragma unroll
            for (int wg = 0; wg < 16; wg++) c += hist[wg][t];
            cnt[t] = c;
        }
        __syncthreads();

        if (warp == 0) {
            int v[8], s[8];
#pragma unroll
            for (int j = 0; j < 8; j++) v[j] = cnt[lane * 8 + j];
            s[7] = v[7];
#pragma unroll
            for (int j = 6; j >= 0; j--) s[j] = s[j + 1] + v[j];
            int suf = s[0];
#pragma unroll
            for (int off = 1; off < 32; off <<= 1) {
                int o = __shfl_down_sync(0xFFFFFFFFu, suf, off);
                if (lane + off < 32) suf += o;
            }
            int above_lanes = suf - s[0];
#pragma unroll
            for (int j = 0; j < 8; j++) {
                int Sj = s[j] + above_lanes;
                int Sn = (j < 7 ? s[j + 1] : 0) + above_lanes;
                if (Sj >= kcur && Sn < kcur) {
                    s_prefix = prefix | ((unsigned)(lane * 8 + j) << shift);
                    s_k = kcur - Sn;
                }
            }
        }
        __syncthreads();
    }

    if (t == 0) {
        d_thr[b] = s_prefix;     // exact key of K-th largest
        d_count[b] = 0;          // reset for next graph replay
        __threadfence();
    }
}

// ---------------------------------------------------------------------------
// mul chunk: one thread = one gate cell x 4 image rows (R7 shape: MLP=4,
// perfectly coalesced 512B/instruction). Reads are L2 hits for this chunk;
// streaming stores (never re-read) minimize L2 pollution of the input.
// ---------------------------------------------------------------------------
__global__ void gate_mul_kernel(const float4* __restrict__ in,
                                float4* __restrict__ out, int batch0) {
    int i  = blockIdx.x * blockDim.x + threadIdx.x;  // [0, 128*128)
    int x4 = i & 127;              // float4 col == gate col
    int gy = i >> 7;               // gate row
    int c  = blockIdx.y;           // channel
    int b  = batch0 + blockIdx.z;  // global batch

    unsigned thr = __ldg(&d_thr[b]);
    float gv = d_gate[b * 16384 + gy * 128 + x4];
    bool alive = f2key(gv) >= thr;

    size_t base = (size_t)(b * 3 + c) * 65536 + (size_t)(4 * gy) * 128 + x4;

    float4 z = make_float4(0.f, 0.f, 0.f, 0.f);
    float4 v0 = z, v1 = z, v2 = z, v3 = z;
    if (alive) {
        float4 t0 = in[base];
        float4 t1 = in[base + 128];
        float4 t2 = in[base + 256];
        float4 t3 = in[base + 384];
        v0.x = t0.x * gv; v0.y = t0.y * gv; v0.z = t0.z * gv; v0.w = t0.w * gv;
        v1.x = t1.x * gv; v1.y = t1.y * gv; v1.z = t1.z * gv; v1.w = t1.w * gv;
        v2.x = t2.x * gv; v2.y = t2.y * gv; v2.z = t2.z * gv; v2.w = t2.w * gv;
        v3.x = t3.x * gv; v3.y = t3.y * gv; v3.z = t3.z * gv; v3.w = t3.w * gv;
    }
    __stcs(&out[base],       v0);
    __stcs(&out[base + 128], v1);
    __stcs(&out[base + 256], v2);
    __stcs(&out[base + 384], v3);
}

// ---------------------------------------------------------------------------
extern "C" void kernel_launch(void* const* d_in, const int* in_sizes, int n_in,
                              void* d_out, int out_size) {
    const float* inp = (const float*)d_in[0];
    const float* wk  = (const float*)d_in[1];
    if (n_in >= 2 && in_sizes[0] == 48) {  // defensive: swap if order flipped
        inp = (const float*)d_in[1];
        wk  = (const float*)d_in[0];
    }

    // 4 chunks x 16 batches: chunk input (50MB) stays L2-resident between
    // its conv and its mul.
    for (int chunk = 0; chunk < 4; chunk++) {
        int batch0 = chunk * 16;
        gate_convsel_kernel<<<512, 512>>>((const float4*)inp, wk, batch0);
        dim3 mgrid(64, 3, 16);
        gate_mul_kernel<<<mgrid, 256>>>((const float4*)inp, (float4*)d_out,
                                        batch0);
    }
}

// round 10
// speedup vs baseline: 1.4647x; 1.4647x over previous
#include <cuda_runtime.h>
#include <cstdint>

// Gate pipeline (2 kernels):
//   K1: conv 4x4/s4 [64,3,512,512] -> gate[64,128,128]; last-arriving block
//       per batch runs the FAST exact K-th-largest radix select as a tail
//       (hidden in the grid drain).
//   K2: out = in * (gate >= thr ? gate : 0), 4x upsample, 3ch bcast.
//       One thread = 1 gate cell x 4 rows (MLP=4), sector-exact read skip.
__device__ float    d_gate[64 * 16384];
__device__ unsigned d_thr[64];
__device__ int      d_count[64];    // zero-init; last block resets (replay-safe)

__device__ __forceinline__ unsigned f2key(float f) {
    unsigned u = __float_as_uint(f);
    return (u & 0x80000000u) ? ~u : (u | 0x80000000u);  // monotone float->uint
}

// ---------------------------------------------------------------------------
// K1: conv + fused fast select. 32 blocks x 512 thr per batch, 64 batches.
// Conv: one thread per gate pixel, 12 coalesced float4 loads (79% DRAM).
// Tail: last block per batch -> register-key radix select (warp-private
// match_any histograms, single-warp shfl suffix scan, 4 barriers/pass).
// ---------------------------------------------------------------------------
__global__ void __launch_bounds__(512) gate_convsel_kernel(
        const float4* __restrict__ in, const float* __restrict__ wk) {
    __shared__ float4 w[12];
    __shared__ unsigned hist[16][256];
    __shared__ int cnt[256];
    __shared__ unsigned s_prefix;
    __shared__ int s_k;
    __shared__ int s_rank;

    const int t = threadIdx.x;
    if (t < 12) w[t] = reinterpret_cast<const float4*>(wk)[t];
    __syncthreads();

    const int b = blockIdx.x >> 5;                  // batch
    const int pix = (blockIdx.x & 31) * 512 + t;    // [0,16384) gate pixel
    const int x = pix & 127;
    const int y = pix >> 7;

    // ---- conv ----
    const float4* base = in + (size_t)b * 196608 + x;
    float sum = 0.0f;
#pragma unroll
    for (int c = 0; c < 3; c++) {
#pragma unroll
        for (int i = 0; i < 4; i++) {
            float4 v = base[c * 65536 + (4 * y + i) * 128];
            float4 ww = w[c * 4 + i];
            sum += v.x * ww.x + v.y * ww.y + v.z * ww.z + v.w * ww.w;
        }
    }
    d_gate[b * 16384 + pix] = sum;

    // ---- arrival: last block of this batch runs the select ----
    __threadfence();
    __syncthreads();
    if (t == 0) s_rank = atomicAdd(&d_count[b], 1);
    __syncthreads();
    if (s_rank != 31) return;

    const int warp = t >> 5;
    const int lane = t & 31;

    // one-shot vectorized key load (L2-hot: just written)
    unsigned key[32];
    const float4* g4 = reinterpret_cast<const float4*>(d_gate + b * 16384);
#pragma unroll
    for (int i = 0; i < 8; i++) {
        float4 v = g4[t + i * 512];
        key[4 * i + 0] = f2key(v.x);
        key[4 * i + 1] = f2key(v.y);
        key[4 * i + 2] = f2key(v.z);
        key[4 * i + 3] = f2key(v.w);
    }

    if (t == 0) { s_prefix = 0u; s_k = 4096; }

#pragma unroll
    for (int pass = 0; pass < 4; pass++) {
        const int shift = 24 - 8 * pass;
        for (int i = t; i < 16 * 256; i += 512)
            (&hist[0][0])[i] = 0u;
        __syncthreads();

        const unsigned pmask = pass ? (0xFFFFFFFFu << (32 - 8 * pass)) : 0u;
        const unsigned prefix = s_prefix;
        const int kcur = s_k;

#pragma unroll
        for (int i = 0; i < 32; i++) {
            unsigned u = key[i];
            unsigned bn = ((u & pmask) == prefix) ? ((u >> shift) & 0xFFu)
                                                  : 0xFFFFFFFFu;
            unsigned same = __match_any_sync(0xFFFFFFFFu, bn);
            if (bn != 0xFFFFFFFFu && lane == (__ffs(same) - 1))
                hist[warp][bn] += __popc(same);      // warp-private
        }
        __syncthreads();

        if (t < 256) {
            int c = 0;
#pragma unroll
            for (int wg = 0; wg < 16; wg++) c += hist[wg][t];
            cnt[t] = c;
        }
        __syncthreads();

        if (warp == 0) {
            int v[8], s[8];
#pragma unroll
            for (int j = 0; j < 8; j++) v[j] = cnt[lane * 8 + j];
            s[7] = v[7];
#pragma unroll
            for (int j = 6; j >= 0; j--) s[j] = s[j + 1] + v[j];
            int suf = s[0];
#pragma unroll
            for (int off = 1; off < 32; off <<= 1) {
                int o = __shfl_down_sync(0xFFFFFFFFu, suf, off);
                if (lane + off < 32) suf += o;
            }
            int above_lanes = suf - s[0];
#pragma unroll
            for (int j = 0; j < 8; j++) {
                int Sj = s[j] + above_lanes;
                int Sn = (j < 7 ? s[j + 1] : 0) + above_lanes;
                if (Sj >= kcur && Sn < kcur) {
                    s_prefix = prefix | ((unsigned)(lane * 8 + j) << shift);
                    s_k = kcur - Sn;
                }
            }
        }
        __syncthreads();
    }

    if (t == 0) {
        d_thr[b] = s_prefix;     // exact key of K-th largest
        d_count[b] = 0;          // reset for next graph replay
        __threadfence();
    }
}

// ---------------------------------------------------------------------------
// K2: out = in * gate. One thread = one gate cell x 4 image rows:
// 1 gate load, 4 independent in loads (MLP=4, predicated off when dead),
// 4 stores. Warp per-instruction access = contiguous 512B. (R7 shape.)
// ---------------------------------------------------------------------------
__global__ void gate_mul_kernel(const float4* __restrict__ in,
                                float4* __restrict__ out) {
    int i  = blockIdx.x * blockDim.x + threadIdx.x;  // [0, 128*128)
    int x4 = i & 127;              // float4 col == gate col
    int gy = i >> 7;               // gate row
    int c  = blockIdx.y;           // channel
    int b  = blockIdx.z;           // batch

    unsigned thr = __ldg(&d_thr[b]);
    float gv = d_gate[b * 16384 + gy * 128 + x4];
    bool alive = f2key(gv) >= thr;

    size_t base = (size_t)(b * 3 + c) * 65536 + (size_t)(4 * gy) * 128 + x4;

    float4 z = make_float4(0.f, 0.f, 0.f, 0.f);
    float4 v0 = z, v1 = z, v2 = z, v3 = z;
    if (alive) {
        float4 t0 = in[base];
        float4 t1 = in[base + 128];
        float4 t2 = in[base + 256];
        float4 t3 = in[base + 384];
        v0.x = t0.x * gv; v0.y = t0.y * gv; v0.z = t0.z * gv; v0.w = t0.w * gv;
        v1.x = t1.x * gv; v1.y = t1.y * gv; v1.z = t1.z * gv; v1.w = t1.w * gv;
        v2.x = t2.x * gv; v2.y = t2.y * gv; v2.z = t2.z * gv; v2.w = t2.w * gv;
        v3.x = t3.x * gv; v3.y = t3.y * gv; v3.z = t3.z * gv; v3.w = t3.w * gv;
    }
    out[base]       = v0;
    out[base + 128] = v1;
    out[base + 256] = v2;
    out[base + 384] = v3;
}

// ---------------------------------------------------------------------------
extern "C" void kernel_launch(void* const* d_in, const int* in_sizes, int n_in,
                              void* d_out, int out_size) {
    const float* inp = (const float*)d_in[0];
    const float* wk  = (const float*)d_in[1];
    if (n_in >= 2 && in_sizes[0] == 48) {  // defensive: swap if order flipped
        inp = (const float*)d_in[1];
        wk  = (const float*)d_in[0];
    }

    // 64 batches x 32 blocks, full-size single launch
    gate_convsel_kernel<<<2048, 512>>>((const float4*)inp, wk);
    // 128*128 gate cells / 256 = 64 blocks; y = 3 channels; z = 64 batches
    dim3 mgrid(64, 3, 64);
    gate_mul_kernel<<<mgrid, 256>>>((const float4*)inp, (float4*)d_out);
}